// round 7
// baseline (speedup 1.0000x reference)
#include <cuda_runtime.h>
#include <cuda_bf16.h>
#include <cstdint>

// Problem constants (from reference)
#define N_NODES 50000
#define N_EDGES 800000
#define NUM_GRAPHS 64
#define F_IN 128
#define F_HID 96
#define F_HID2 48
#define F_OUT 32
#define ELL_W 64   // max in-degree slot (Poisson(16) over 50k nodes: max ~40)

// ---------------- Scratch (device globals; no allocation allowed) ----------
__device__ __align__(16) float d_P[N_NODES * F_HID];   // ping buffer
__device__ __align__(16) float d_Q[N_NODES * F_HID];   // pong buffer
__device__ int   d_cnt[N_NODES];
__device__ int   d_ell[N_NODES * ELL_W];
__device__ int   d_is64;   // 1 if edge_index/batch are int64, 0 if int32

// ---------------- Dtype detect + cnt zero (fused) ----------------------------
__global__ void k_detect_zero(const unsigned int* __restrict__ w, int* __restrict__ cnt) {
    int i = blockIdx.x * blockDim.x + threadIdx.x;
    if (i < N_NODES) cnt[i] = 0;
    if (i == 0) {
        int is64 = 1;
        for (int k = 0; k < 16; k++)
            if (w[2 * k + 1] != 0u) { is64 = 0; break; }
        d_is64 = is64;
    }
}

__device__ __forceinline__ int load_idx(const void* p, long long i) {
    if (d_is64) return (int)((const long long*)p)[i];
    return ((const int*)p)[i];
}

__device__ __forceinline__ float dinv_of(int c) {
    return rsqrtf(1.0f + (float)min(c, ELL_W));
}

// ---------------- ELL build --------------------------------------------------
__global__ void k_prep_ell(const void* __restrict__ ei,
                           int* __restrict__ cnt, int* __restrict__ ell) {
    int e = blockIdx.x * blockDim.x + threadIdx.x;
    if (e < N_EDGES) {
        int s = load_idx(ei, e);
        int d = load_idx(ei, (long long)N_EDGES + e);
        s = min(max(s, 0), N_NODES - 1);
        d = min(max(d, 0), N_NODES - 1);
        int slot = atomicAdd(&cnt[d], 1);
        if (slot < ELL_W) ell[d * ELL_W + slot] = s;
    }
}

// ---------------- Fused GEMM (packed f32x2 FMA, BM=64/128thr) ----------------
// h = act(X) @ W ; epilogue G[row] = h * dinv[row] (dinv from cnt inline)
template <int K, int N, bool ACT>
__global__ __launch_bounds__(128)
void k_gemm(const float* __restrict__ X, const float* __restrict__ W,
            const float* __restrict__ bias, const int* __restrict__ cnt,
            float* __restrict__ G) {
    constexpr int BM = 64, BK = 16, TM = 8, TN = N / 16;
    __shared__ float  Xs[BK][BM + 4];        // k-major, padded
    __shared__ float2 Ws2[BK][N];            // pre-splatted {w,w}

    const int tid = threadIdx.x;
    const int tx = tid & 15;     // 16 column groups of TN consecutive cols
    const int ty = tid >> 4;     // 8 row groups of TM rows
    const int row0 = blockIdx.x * BM;
    const int m0 = ty * TM;

    unsigned long long acc[TM / 2][TN];
#pragma unroll
    for (int i = 0; i < TM / 2; i++)
#pragma unroll
        for (int n = 0; n < TN; n++) acc[i][n] = 0ULL;

    for (int kt = 0; kt < K; kt += BK) {
        // X tile: BM x BK = 1024 elems, 8 per thread (2 float4)
        {
            int r = tid >> 1;             // 0..63
            int kc = (tid & 1) * 8;       // 0 or 8
            int grow = row0 + r;
#pragma unroll
            for (int h = 0; h < 2; h++) {
                float4 v = make_float4(0.f, 0.f, 0.f, 0.f);
                if (grow < N_NODES)
                    v = *(const float4*)&X[(size_t)grow * K + kt + kc + 4 * h];
                if (ACT) {
                    v.x = fmaxf(v.x + bias[kt + kc + 4 * h + 0], 0.f);
                    v.y = fmaxf(v.y + bias[kt + kc + 4 * h + 1], 0.f);
                    v.z = fmaxf(v.z + bias[kt + kc + 4 * h + 2], 0.f);
                    v.w = fmaxf(v.w + bias[kt + kc + 4 * h + 3], 0.f);
                }
                Xs[kc + 4 * h + 0][r] = v.x;
                Xs[kc + 4 * h + 1][r] = v.y;
                Xs[kc + 4 * h + 2][r] = v.z;
                Xs[kc + 4 * h + 3][r] = v.w;
            }
        }
        // W tile: BK x N, splatted
        for (int idx = tid; idx < BK * N; idx += 128) {
            int kk = idx / N, n = idx - kk * N;
            float w = W[(size_t)(kt + kk) * N + n];
            Ws2[kk][n] = make_float2(w, w);
        }
        __syncthreads();

#pragma unroll
        for (int k = 0; k < BK; k++) {
            // a: TM=8 consecutive rows -> 2x LDS.128 -> 4 packed pairs
            float4 c0 = *(const float4*)&Xs[k][m0];
            float4 c1 = *(const float4*)&Xs[k][m0 + 4];
            unsigned long long a2[TM / 2];
            a2[0] = *(const unsigned long long*)&c0.x;
            a2[1] = *(const unsigned long long*)&c0.z;
            a2[2] = *(const unsigned long long*)&c1.x;
            a2[3] = *(const unsigned long long*)&c1.z;
            unsigned long long b2[TN];
#pragma unroll
            for (int n = 0; n < TN; n++)
                b2[n] = *(const unsigned long long*)&Ws2[k][tx * TN + n];
#pragma unroll
            for (int i = 0; i < TM / 2; i++)
#pragma unroll
                for (int n = 0; n < TN; n++)
                    asm("fma.rn.f32x2 %0, %1, %2, %0;"
                        : "+l"(acc[i][n]) : "l"(a2[i]), "l"(b2[n]));
        }
        __syncthreads();
    }

    // epilogue: unpack pairs, scale by dinv[row], store
#pragma unroll
    for (int i = 0; i < TM / 2; i++) {
        int r_lo = row0 + m0 + 2 * i;
        int r_hi = r_lo + 1;
        float di_lo = (r_lo < N_NODES) ? dinv_of(cnt[r_lo]) : 0.f;
        float di_hi = (r_hi < N_NODES) ? dinv_of(cnt[r_hi]) : 0.f;
#pragma unroll
        for (int n = 0; n < TN; n++) {
            float lo, hi;
            asm("mov.b64 {%0, %1}, %2;" : "=f"(lo), "=f"(hi) : "l"(acc[i][n]));
            int c = tx * TN + n;
            if (r_lo < N_NODES) G[(size_t)r_lo * N + c] = lo * di_lo;
            if (r_hi < N_NODES) G[(size_t)r_hi * N + c] = hi * di_hi;
        }
    }
}

// ---------------- ELL gather aggregation (float2, multi-node blocks) ---------
// OUT[n] = dinv[n] * (G[n] + sum_e G[ell[n][e]])
template <int F, int NPB>
__global__ __launch_bounds__((F / 2) * NPB)
void k_gather(const int* __restrict__ cnt, const int* __restrict__ ell,
              const float2* __restrict__ G2, float2* __restrict__ OUT2) {
    constexpr int T = F / 2;
    __shared__ int sh[NPB][ELL_W];
    __shared__ int shc[NPB];

    const int tid = threadIdx.x;
    const int g = tid / T;
    const int f = tid - g * T;
    const int n = blockIdx.x * NPB + g;
    const bool valid = (n < N_NODES);

    int c = 0;
    if (valid) {
        c = min(cnt[n], ELL_W);
        if (f == 0) shc[g] = c;
        for (int i = f; i < c; i += T) sh[g][i] = ell[n * ELL_W + i];
    }
    __syncthreads();
    if (!valid) return;
    c = shc[g];

    float2 a = G2[(size_t)n * T + f];   // self loop
    float accx = a.x, accy = a.y;
    int e = 0;
    for (; e + 4 <= c; e += 4) {
        int s0 = sh[g][e], s1 = sh[g][e + 1], s2 = sh[g][e + 2], s3 = sh[g][e + 3];
        float2 v0 = G2[(size_t)s0 * T + f];
        float2 v1 = G2[(size_t)s1 * T + f];
        float2 v2 = G2[(size_t)s2 * T + f];
        float2 v3 = G2[(size_t)s3 * T + f];
        accx += (v0.x + v1.x) + (v2.x + v3.x);
        accy += (v0.y + v1.y) + (v2.y + v3.y);
    }
    for (; e < c; e++) {
        float2 v = G2[(size_t)sh[g][e] * T + f];
        accx += v.x; accy += v.y;
    }
    float di = dinv_of(c);
    OUT2[(size_t)n * T + f] = make_float2(accx * di, accy * di);
}

// ---------------- Fused pooling (batch is sorted -> binary search ranges) ----
__global__ __launch_bounds__(256)
void k_pool(const float* __restrict__ A, const void* __restrict__ batch,
            const float* __restrict__ b3, float* __restrict__ out) {
    __shared__ float red[8][F_OUT];
    __shared__ int bounds[2];
    const int b = blockIdx.x;
    const int tid = threadIdx.x;
    const int warp = tid >> 5;
    const int lane = tid & 31;

    if (tid < 2) {
        int target = b + tid;
        int lo = 0, hi = N_NODES;
        while (lo < hi) {
            int mid = (lo + hi) >> 1;
            int v = load_idx(batch, mid);
            if (v < target) lo = mid + 1; else hi = mid;
        }
        bounds[tid] = lo;
    }
    __syncthreads();
    const int beg = bounds[0], end = bounds[1];

    float bias = b3[lane];
    float acc = 0.0f;
    for (int r = beg + warp; r < end; r += 8)
        acc += fmaxf(A[(size_t)r * F_OUT + lane] + bias, 0.0f);
    red[warp][lane] = acc;
    __syncthreads();
    if (warp == 0) {
        float s = red[0][lane];
#pragma unroll
        for (int w = 1; w < 8; w++) s += red[w][lane];
        float n = (float)(end - beg);
        out[b * F_OUT + lane] = s / fmaxf(n, 1.0f);
    }
}

// ---------------- Launch ------------------------------------------------------
extern "C" void kernel_launch(void* const* d_in, const int* in_sizes, int n_in,
                              void* d_out, int out_size) {
    const float* x   = (const float*)d_in[0];
    const void*  ei  = d_in[1];
    const void*  bat = d_in[2];
    const float* W1  = (const float*)d_in[3];
    const float* b1  = (const float*)d_in[4];
    const float* W2  = (const float*)d_in[5];
    const float* b2  = (const float*)d_in[6];
    const float* W3  = (const float*)d_in[7];
    const float* b3  = (const float*)d_in[8];
    float* out = (float*)d_out;

    float *P, *Q;
    int *cnt, *ell;
    cudaGetSymbolAddress((void**)&P,   d_P);
    cudaGetSymbolAddress((void**)&Q,   d_Q);
    cudaGetSymbolAddress((void**)&cnt, d_cnt);
    cudaGetSymbolAddress((void**)&ell, d_ell);

    const int TB = 256;
    const int NB = (N_NODES + TB - 1) / TB;
    const int EB = (N_EDGES + TB - 1) / TB;

    // ELL build
    k_detect_zero<<<NB, TB>>>((const unsigned int*)ei, cnt);
    k_prep_ell<<<EB, TB>>>(ei, cnt, ell);

    const int gemm_blocks = (N_NODES + 63) / 64;

    // Layer 1: x[128] -> 96
    k_gemm<F_IN, F_HID, false><<<gemm_blocks, 128>>>(x, W1, nullptr, cnt, P);
    k_gather<F_HID, 2><<<(N_NODES + 1) / 2, (F_HID / 2) * 2>>>(cnt, ell, (const float2*)P, (float2*)Q);

    // Layer 2: relu(Q + b1)[96] -> 48
    k_gemm<F_HID, F_HID2, true><<<gemm_blocks, 128>>>(Q, W2, b1, cnt, P);
    k_gather<F_HID2, 4><<<(N_NODES + 3) / 4, (F_HID2 / 2) * 4>>>(cnt, ell, (const float2*)P, (float2*)Q);

    // Layer 3: relu(Q + b2)[48] -> 32
    k_gemm<F_HID2, F_OUT, true><<<gemm_blocks, 128>>>(Q, W3, b2, cnt, P);
    k_gather<F_OUT, 8><<<(N_NODES + 7) / 8, (F_OUT / 2) * 8>>>(cnt, ell, (const float2*)P, (float2*)Q);

    // Global mean pool (batch sorted -> per-graph contiguous ranges)
    k_pool<<<NUM_GRAPHS, 256>>>(Q, bat, b3, out);
}

// round 8
// speedup vs baseline: 1.1003x; 1.1003x over previous
#include <cuda_runtime.h>
#include <cuda_bf16.h>
#include <cstdint>

// Problem constants (from reference)
#define N_NODES 50000
#define N_EDGES 800000
#define NUM_GRAPHS 64
#define F_IN 128
#define F_HID 96
#define F_HID2 48
#define F_OUT 32
#define ELL_W 64   // max in-degree slot (Poisson(16) over 50k nodes: max ~40)

// ---------------- Scratch (device globals; no allocation allowed) ----------
__device__ __align__(16) float d_P[N_NODES * F_HID];   // ping buffer
__device__ __align__(16) float d_Q[N_NODES * F_HID];   // pong buffer
__device__ int   d_cnt[N_NODES];
__device__ __align__(16) int d_ell[N_NODES * ELL_W];
__device__ int   d_is64;   // 1 if edge_index/batch are int64, 0 if int32

// ---------------- Dtype detect + cnt zero (fused) ----------------------------
__global__ void k_detect_zero(const unsigned int* __restrict__ w, int* __restrict__ cnt) {
    int i = blockIdx.x * blockDim.x + threadIdx.x;
    if (i < N_NODES) cnt[i] = 0;
    if (i == 0) {
        int is64 = 1;
        for (int k = 0; k < 16; k++)
            if (w[2 * k + 1] != 0u) { is64 = 0; break; }
        d_is64 = is64;
    }
}

__device__ __forceinline__ int load_idx(const void* p, long long i) {
    if (d_is64) return (int)((const long long*)p)[i];
    return ((const int*)p)[i];
}

__device__ __forceinline__ float dinv_of(int c) {
    return rsqrtf(1.0f + (float)min(c, ELL_W));
}

// ---------------- ELL build --------------------------------------------------
__global__ void k_prep_ell(const void* __restrict__ ei,
                           int* __restrict__ cnt, int* __restrict__ ell) {
    int e = blockIdx.x * blockDim.x + threadIdx.x;
    if (e < N_EDGES) {
        int s = load_idx(ei, e);
        int d = load_idx(ei, (long long)N_EDGES + e);
        s = min(max(s, 0), N_NODES - 1);
        d = min(max(d, 0), N_NODES - 1);
        int slot = atomicAdd(&cnt[d], 1);
        if (slot < ELL_W) ell[d * ELL_W + slot] = s;
    }
}

// ---------------- Fused GEMM (R6 geometry: BM=128/BK=8/256thr, splat W) ------
// h = act(X) @ W ; epilogue G[row] = h * dinv[row] (dinv from cnt inline)
template <int K, int N, bool ACT>
__global__ __launch_bounds__(256)
void k_gemm(const float* __restrict__ X, const float* __restrict__ W,
            const float* __restrict__ bias, const int* __restrict__ cnt,
            float* __restrict__ G) {
    constexpr int BM = 128, BK = 8, TM = 8, TN = N / 16;
    __shared__ float  Xs[BK][BM + 4];   // k-major, padded
    __shared__ float2 Ws2[BK][N];       // pre-splatted {w,w}

    const int tid = threadIdx.x;
    const int tx = tid & 15;    // 16 column groups of TN consecutive cols
    const int ty = tid >> 4;    // 16 row groups of TM rows
    const int row0 = blockIdx.x * BM;
    const int m0 = ty * TM;

    unsigned long long acc[TM / 2][TN];
#pragma unroll
    for (int i = 0; i < TM / 2; i++)
#pragma unroll
        for (int n = 0; n < TN; n++) acc[i][n] = 0ULL;

    for (int kt = 0; kt < K; kt += BK) {
        // X tile (BM x BK), transposed into Xs[k][m]; float4 per thread
        {
            int r = tid >> 1;            // 0..127
            int kc = (tid & 1) * 4;      // 0 or 4
            int grow = row0 + r;
            float4 v = make_float4(0.f, 0.f, 0.f, 0.f);
            if (grow < N_NODES)
                v = *(const float4*)&X[(size_t)grow * K + kt + kc];
            if (ACT) {
                v.x = fmaxf(v.x + bias[kt + kc + 0], 0.f);
                v.y = fmaxf(v.y + bias[kt + kc + 1], 0.f);
                v.z = fmaxf(v.z + bias[kt + kc + 2], 0.f);
                v.w = fmaxf(v.w + bias[kt + kc + 3], 0.f);
            }
            Xs[kc + 0][r] = v.x;
            Xs[kc + 1][r] = v.y;
            Xs[kc + 2][r] = v.z;
            Xs[kc + 3][r] = v.w;
        }
        // W tile (BK x N), splatted
        for (int idx = tid; idx < BK * N; idx += 256) {
            int kk = idx / N, n = idx - kk * N;
            float w = W[(size_t)(kt + kk) * N + n];
            Ws2[kk][n] = make_float2(w, w);
        }
        __syncthreads();

#pragma unroll
        for (int k = 0; k < BK; k++) {
            float4 c0 = *(const float4*)&Xs[k][m0];
            float4 c1 = *(const float4*)&Xs[k][m0 + 4];
            unsigned long long a2[TM / 2];
            a2[0] = *(const unsigned long long*)&c0.x;
            a2[1] = *(const unsigned long long*)&c0.z;
            a2[2] = *(const unsigned long long*)&c1.x;
            a2[3] = *(const unsigned long long*)&c1.z;
            unsigned long long b2[TN];
#pragma unroll
            for (int n = 0; n < TN; n++)
                b2[n] = *(const unsigned long long*)&Ws2[k][tx * TN + n];
#pragma unroll
            for (int i = 0; i < TM / 2; i++)
#pragma unroll
                for (int n = 0; n < TN; n++)
                    asm("fma.rn.f32x2 %0, %1, %2, %0;"
                        : "+l"(acc[i][n]) : "l"(a2[i]), "l"(b2[n]));
        }
        __syncthreads();
    }

    // epilogue: unpack pairs, scale by dinv[row], store
#pragma unroll
    for (int i = 0; i < TM / 2; i++) {
        int r_lo = row0 + m0 + 2 * i;
        int r_hi = r_lo + 1;
        float di_lo = (r_lo < N_NODES) ? dinv_of(cnt[r_lo]) : 0.f;
        float di_hi = (r_hi < N_NODES) ? dinv_of(cnt[r_hi]) : 0.f;
#pragma unroll
        for (int n = 0; n < TN; n++) {
            float lo, hi;
            asm("mov.b64 {%0, %1}, %2;" : "=f"(lo), "=f"(hi) : "l"(acc[i][n]));
            int c = tx * TN + n;
            if (r_lo < N_NODES) G[(size_t)r_lo * N + c] = lo * di_lo;
            if (r_hi < N_NODES) G[(size_t)r_hi * N + c] = hi * di_hi;
        }
    }
}

// ---------------- ELL gather aggregation (float4, multi-node blocks) ---------
// OUT[n] = dinv[n] * (G[n] + sum_e G[ell[n][e]])
// T = F/4 threads per node (each handles a float4), NPB nodes per block.
template <int F, int NPB>
__global__ __launch_bounds__((F / 4) * NPB)
void k_gather(const int* __restrict__ cnt, const int* __restrict__ ell,
              const float4* __restrict__ G4, float4* __restrict__ OUT4) {
    constexpr int T = F / 4;
    __shared__ int4 sh[NPB][ELL_W / 4];
    __shared__ int shc[NPB];

    const int tid = threadIdx.x;
    const int g = tid / T;
    const int f = tid - g * T;
    const int n = blockIdx.x * NPB + g;
    const bool valid = (n < N_NODES);

    int c = 0;
    if (valid) {
        c = min(cnt[n], ELL_W);
        if (f == 0) shc[g] = c;
        // load edge list as int4 (ELL rows are 16B-aligned: ELL_W=64)
        const int4* row = (const int4*)&ell[n * ELL_W];
        for (int i = f; i < (c + 3) / 4; i += T) sh[g][i] = row[i];
    }
    __syncthreads();
    if (!valid) return;
    c = shc[g];

    float4 a = G4[(size_t)n * T + f];   // self loop
    float ax = a.x, ay = a.y, az = a.z, aw = a.w;
    int e = 0;
    for (; e + 4 <= c; e += 4) {
        int4 s4 = sh[g][e >> 2];
        float4 v0 = G4[(size_t)s4.x * T + f];
        float4 v1 = G4[(size_t)s4.y * T + f];
        float4 v2 = G4[(size_t)s4.z * T + f];
        float4 v3 = G4[(size_t)s4.w * T + f];
        ax += (v0.x + v1.x) + (v2.x + v3.x);
        ay += (v0.y + v1.y) + (v2.y + v3.y);
        az += (v0.z + v1.z) + (v2.z + v3.z);
        aw += (v0.w + v1.w) + (v2.w + v3.w);
    }
    if (e < c) {
        int4 s4 = sh[g][e >> 2];
        int rem = c - e;
        const int ss[3] = {s4.x, s4.y, s4.z};
        for (int j = 0; j < rem; j++) {
            float4 v = G4[(size_t)ss[j] * T + f];
            ax += v.x; ay += v.y; az += v.z; aw += v.w;
        }
    }
    float di = dinv_of(c);
    OUT4[(size_t)n * T + f] = make_float4(ax * di, ay * di, az * di, aw * di);
}

// ---------------- Fused pooling (batch is sorted -> binary search ranges) ----
__global__ __launch_bounds__(256)
void k_pool(const float* __restrict__ A, const void* __restrict__ batch,
            const float* __restrict__ b3, float* __restrict__ out) {
    __shared__ float red[8][F_OUT];
    __shared__ int bounds[2];
    const int b = blockIdx.x;
    const int tid = threadIdx.x;
    const int warp = tid >> 5;
    const int lane = tid & 31;

    if (tid < 2) {
        int target = b + tid;
        int lo = 0, hi = N_NODES;
        while (lo < hi) {
            int mid = (lo + hi) >> 1;
            int v = load_idx(batch, mid);
            if (v < target) lo = mid + 1; else hi = mid;
        }
        bounds[tid] = lo;
    }
    __syncthreads();
    const int beg = bounds[0], end = bounds[1];

    float bias = b3[lane];
    float acc = 0.0f;
    for (int r = beg + warp; r < end; r += 8)
        acc += fmaxf(A[(size_t)r * F_OUT + lane] + bias, 0.0f);
    red[warp][lane] = acc;
    __syncthreads();
    if (warp == 0) {
        float s = red[0][lane];
#pragma unroll
        for (int w = 1; w < 8; w++) s += red[w][lane];
        float n = (float)(end - beg);
        out[b * F_OUT + lane] = s / fmaxf(n, 1.0f);
    }
}

// ---------------- Launch ------------------------------------------------------
extern "C" void kernel_launch(void* const* d_in, const int* in_sizes, int n_in,
                              void* d_out, int out_size) {
    const float* x   = (const float*)d_in[0];
    const void*  ei  = d_in[1];
    const void*  bat = d_in[2];
    const float* W1  = (const float*)d_in[3];
    const float* b1  = (const float*)d_in[4];
    const float* W2  = (const float*)d_in[5];
    const float* b2  = (const float*)d_in[6];
    const float* W3  = (const float*)d_in[7];
    const float* b3  = (const float*)d_in[8];
    float* out = (float*)d_out;

    float *P, *Q;
    int *cnt, *ell;
    cudaGetSymbolAddress((void**)&P,   d_P);
    cudaGetSymbolAddress((void**)&Q,   d_Q);
    cudaGetSymbolAddress((void**)&cnt, d_cnt);
    cudaGetSymbolAddress((void**)&ell, d_ell);

    const int TB = 256;
    const int NB = (N_NODES + TB - 1) / TB;
    const int EB = (N_EDGES + TB - 1) / TB;

    // ELL build
    k_detect_zero<<<NB, TB>>>((const unsigned int*)ei, cnt);
    k_prep_ell<<<EB, TB>>>(ei, cnt, ell);

    const int gemm_blocks = (N_NODES + 127) / 128;

    // Layer 1: x[128] -> 96
    k_gemm<F_IN, F_HID, false><<<gemm_blocks, 256>>>(x, W1, nullptr, cnt, P);
    k_gather<F_HID, 4><<<(N_NODES + 3) / 4, (F_HID / 4) * 4>>>(cnt, ell, (const float4*)P, (float4*)Q);

    // Layer 2: relu(Q + b1)[96] -> 48
    k_gemm<F_HID, F_HID2, true><<<gemm_blocks, 256>>>(Q, W2, b1, cnt, P);
    k_gather<F_HID2, 8><<<(N_NODES + 7) / 8, (F_HID2 / 4) * 8>>>(cnt, ell, (const float4*)P, (float4*)Q);

    // Layer 3: relu(Q + b2)[48] -> 32
    k_gemm<F_HID2, F_OUT, true><<<gemm_blocks, 256>>>(Q, W3, b2, cnt, P);
    k_gather<F_OUT, 16><<<(N_NODES + 15) / 16, (F_OUT / 4) * 16>>>(cnt, ell, (const float4*)P, (float4*)Q);

    // Global mean pool (batch sorted -> per-graph contiguous ranges)
    k_pool<<<NUM_GRAPHS, 256>>>(Q, bat, b3, out);
}